// round 2
// baseline (speedup 1.0000x reference)
#include <cuda_runtime.h>

#define N_NODES 10000
#define N_EDGES 320000
#define N_GRAPHS 64
#define KCHEB 10
#define IN_C 128
#define HID_C 256
#define OUT_C 128

// ---------------- scratch (static device globals; no allocs) ----------------
__device__ float g_Tcat[(size_t)N_NODES * KCHEB * HID_C];  // Chebyshev term stack
__device__ float g_h[(size_t)N_NODES * HID_C];             // layer output (post ReLU)
__device__ float g_deg[N_NODES];
__device__ float g_dis[N_NODES];
__device__ int   g_rowcnt[N_NODES];
__device__ int   g_rowptr[N_NODES + 1];
__device__ int   g_cursor[N_NODES];
__device__ int   g_srcs[N_EDGES];
__device__ float g_ws[N_EDGES];
__device__ float g_pool[N_GRAPHS * HID_C];
__device__ float g_gcnt[N_GRAPHS];
__device__ int   g_is64;   // 1 if index tensors are int64, 0 if int32

// ---------------- dtype detection ----------------
// If edge_index is int64 (little-endian, node ids < 2^31), every odd 32-bit
// word is zero. If int32, odd words are random node ids — P(all 64 zero) ~ 0.
__global__ void k_detect(const int* __restrict__ ei_w) {
    if (threadIdx.x == 0 && blockIdx.x == 0) {
        int all0 = 1;
        for (int i = 0; i < 64; i++)
            if (ei_w[2 * i + 1] != 0) all0 = 0;
        g_is64 = all0;
    }
}

// half: 0 = src row, 1 = dst row of edge_index; e = edge id
__device__ __forceinline__ int ld_edge(const int* __restrict__ w, int half, int e) {
    if (g_is64) return w[((size_t)half * N_EDGES + e) * 2];
    return w[half * N_EDGES + e];
}
__device__ __forceinline__ int ld_batch(const int* __restrict__ w, int n) {
    if (g_is64) return w[2 * n];
    return w[n];
}

// ---------------- prep kernels ----------------
__global__ void k_zero_prep() {
    int i = blockIdx.x * blockDim.x + threadIdx.x;
    if (i < N_NODES) { g_deg[i] = 0.f; g_rowcnt[i] = 0; }
    if (i < N_GRAPHS) g_gcnt[i] = 0.f;
    if (i < N_GRAPHS * HID_C) g_pool[i] = 0.f;
}

__global__ void k_count(const int* __restrict__ ei) {
    int e = blockIdx.x * blockDim.x + threadIdx.x;
    if (e >= N_EDGES) return;
    int s = ld_edge(ei, 0, e);
    int d = ld_edge(ei, 1, e);
    atomicAdd(&g_deg[s], 1.f);
    atomicAdd(&g_rowcnt[d], 1);
}

__global__ void k_dis() {
    int i = blockIdx.x * blockDim.x + threadIdx.x;
    if (i >= N_NODES) return;
    float d = g_deg[i];
    g_dis[i] = (d > 0.f) ? rsqrtf(d) : 0.f;
}

// single-block exclusive scan of g_rowcnt -> g_rowptr (and g_cursor)
__global__ void k_scan() {
    __shared__ int sums[1024];
    int tid = threadIdx.x;
    const int per = (N_NODES + 1023) / 1024;  // 10
    int start = tid * per;
    int local = 0;
    for (int i = 0; i < per; i++) {
        int idx = start + i;
        if (idx < N_NODES) local += g_rowcnt[idx];
    }
    sums[tid] = local;
    __syncthreads();
    for (int off = 1; off < 1024; off <<= 1) {
        int v = 0;
        if (tid >= off) v = sums[tid - off];
        __syncthreads();
        if (tid >= off) sums[tid] += v;
        __syncthreads();
    }
    int prefix = (tid == 0) ? 0 : sums[tid - 1];
    for (int i = 0; i < per; i++) {
        int idx = start + i;
        if (idx < N_NODES) {
            g_rowptr[idx] = prefix;
            g_cursor[idx] = prefix;
            prefix += g_rowcnt[idx];
        }
    }
    if (tid == 1023) g_rowptr[N_NODES] = sums[1023];
}

__global__ void k_fill(const int* __restrict__ ei) {
    int e = blockIdx.x * blockDim.x + threadIdx.x;
    if (e >= N_EDGES) return;
    int s = ld_edge(ei, 0, e);
    int d = ld_edge(ei, 1, e);
    int pos = atomicAdd(&g_cursor[d], 1);
    g_srcs[pos] = s;
    g_ws[pos] = -g_dis[s] * g_dis[d];
}

// ---------------- copies into the Chebyshev stack ----------------
__global__ void k_copy_x(const float* __restrict__ x) {
    int i = blockIdx.x * blockDim.x + threadIdx.x;
    if (i >= N_NODES * IN_C) return;
    int n = i / IN_C, c = i % IN_C;
    g_Tcat[(size_t)n * (KCHEB * IN_C) + c] = x[i];
}

__global__ void k_copy_h() {
    int i = blockIdx.x * blockDim.x + threadIdx.x;
    if (i >= N_NODES * HID_C) return;
    int n = i / HID_C, c = i % HID_C;
    g_Tcat[(size_t)n * (KCHEB * HID_C) + c] = g_h[i];
}

// ---------------- Chebyshev propagation (CSR gather, no atomics) ----------------
// y[n,c] = alpha * sum_{e in row n} w_e * x[src_e, c]  (+ beta * other[n,c])
// operands live inside g_Tcat at the given column offsets, row stride ld.
__global__ void k_prop(int xoff, int yoff, int ooff, int ld, float alpha, float beta) {
    int n = blockIdx.x;
    int c = threadIdx.x;
    int C = blockDim.x;
    __shared__ int   s_src[128];
    __shared__ float s_w[128];
    int beg = g_rowptr[n], end = g_rowptr[n + 1];
    float acc = 0.f;
    for (int base = beg; base < end; base += 128) {
        int cnt = min(128, end - base);
        __syncthreads();
        for (int i = c; i < cnt; i += C) {
            s_src[i] = g_srcs[base + i];
            s_w[i] = g_ws[base + i];
        }
        __syncthreads();
        for (int i = 0; i < cnt; i++)
            acc += s_w[i] * g_Tcat[(size_t)s_src[i] * ld + xoff + c];
    }
    float r = alpha * acc;
    if (beta != 0.f) r += beta * g_Tcat[(size_t)n * ld + ooff + c];
    g_Tcat[(size_t)n * ld + yoff + c] = r;
}

// ---------------- fused big GEMM: g_h = relu(g_Tcat[M,Kd] @ W[Kd,256] + b) ----------------
// BM=128 BN=64 BK=16, 256 threads, 8x4 micro-tile.
__global__ void __launch_bounds__(256) k_gemm(const float* __restrict__ B,
                                              const float* __restrict__ bias,
                                              int lda, int Kd) {
    const int BM = 128, BN = 64, BK = 16;
    __shared__ float As[BK][BM];
    __shared__ float Bs[BK][BN];
    int row0 = blockIdx.y * BM, col0 = blockIdx.x * BN;
    int tid = threadIdx.x;
    int tx = tid & 15, ty = tid >> 4;
    float acc[8][4] = {};
    for (int k0 = 0; k0 < Kd; k0 += BK) {
        // load A tile (128x16), store transposed
#pragma unroll
        for (int p = 0; p < 2; p++) {
            int r = p * 64 + (tid >> 2);
            int cc = (tid & 3) * 4;
            int gr = row0 + r;
            float4 v = make_float4(0.f, 0.f, 0.f, 0.f);
            if (gr < N_NODES)
                v = *(const float4*)&g_Tcat[(size_t)gr * lda + k0 + cc];
            As[cc + 0][r] = v.x;
            As[cc + 1][r] = v.y;
            As[cc + 2][r] = v.z;
            As[cc + 3][r] = v.w;
        }
        // load B tile (16x64)
        {
            int r = tid >> 4;
            int cc = (tid & 15) * 4;
            float4 v = *(const float4*)&B[(size_t)(k0 + r) * HID_C + col0 + cc];
            *(float4*)&Bs[r][cc] = v;
        }
        __syncthreads();
#pragma unroll
        for (int kk = 0; kk < BK; kk++) {
            float a[8], b[4];
#pragma unroll
            for (int i = 0; i < 8; i++) a[i] = As[kk][ty * 8 + i];
#pragma unroll
            for (int j = 0; j < 4; j++) b[j] = Bs[kk][tx * 4 + j];
#pragma unroll
            for (int i = 0; i < 8; i++)
#pragma unroll
                for (int j = 0; j < 4; j++) acc[i][j] += a[i] * b[j];
        }
        __syncthreads();
    }
#pragma unroll
    for (int i = 0; i < 8; i++) {
        int gr = row0 + ty * 8 + i;
        if (gr >= N_NODES) continue;
#pragma unroll
        for (int j = 0; j < 4; j++) {
            int gc = col0 + tx * 4 + j;
            float v = acc[i][j] + bias[gc];
            v = fmaxf(v, 0.f);
            g_h[(size_t)gr * HID_C + gc] = v;
        }
    }
}

// ---------------- pooling + output GEMM ----------------
__global__ void k_pool(const int* __restrict__ batch) {
    int n = blockIdx.x;
    int g = ld_batch(batch, n);
    if (threadIdx.x == 0) atomicAdd(&g_gcnt[g], 1.f);
    for (int c = threadIdx.x; c < HID_C; c += blockDim.x)
        atomicAdd(&g_pool[g * HID_C + c], g_h[(size_t)n * HID_C + c]);
}

__global__ void k_out(const float* __restrict__ Wout, const float* __restrict__ bout,
                      float* __restrict__ out) {
    int g = blockIdx.x, o = threadIdx.x;
    float cn = fmaxf(g_gcnt[g], 1.f);
    float acc = 0.f;
    for (int k = 0; k < HID_C; k++)
        acc += g_pool[g * HID_C + k] * Wout[k * OUT_C + o];
    out[g * OUT_C + o] = acc / cn + bout[o];
}

// ---------------- driver ----------------
extern "C" void kernel_launch(void* const* d_in, const int* in_sizes, int n_in,
                              void* d_out, int out_size) {
    const float* x = (const float*)d_in[0];
    const float* W0 = (const float*)d_in[1];
    const float* b0 = (const float*)d_in[2];
    const float* W1 = (const float*)d_in[3];
    const float* b1 = (const float*)d_in[4];
    const float* W2 = (const float*)d_in[5];
    const float* b2 = (const float*)d_in[6];
    const float* Wout = (const float*)d_in[7];
    const float* bout = (const float*)d_in[8];
    const int* ei = (const int*)d_in[9];      // int32 or int64 words — detected
    const int* batch = (const int*)d_in[10];  // same dtype as ei
    float* out = (float*)d_out;

    // prep: dtype detect, degree, dst histogram, scan -> CSR, fill
    k_detect<<<1, 32>>>(ei);
    k_zero_prep<<<64, 256>>>();
    k_count<<<(N_EDGES + 255) / 256, 256>>>(ei);
    k_dis<<<(N_NODES + 255) / 256, 256>>>();
    k_scan<<<1, 1024>>>();
    k_fill<<<(N_EDGES + 255) / 256, 256>>>(ei);

    dim3 ggrid(HID_C / 64, (N_NODES + 127) / 128);

    // ----- layer 0 (C_in = 128) -----
    {
        const int C = IN_C, ld = KCHEB * IN_C;
        k_copy_x<<<(N_NODES * IN_C + 255) / 256, 256>>>(x);
        for (int k = 1; k < KCHEB; k++) {
            float alpha = (k == 1) ? 1.f : 2.f;
            float beta = (k >= 2) ? -1.f : 0.f;
            int ooff = (k >= 2) ? (k - 2) * C : 0;
            k_prop<<<N_NODES, C>>>((k - 1) * C, k * C, ooff, ld, alpha, beta);
        }
        k_gemm<<<ggrid, 256>>>(W0, b0, ld, ld);
    }

    // ----- layers 1, 2 (C_in = 256) -----
    const float* Ws[2] = {W1, W2};
    const float* bs[2] = {b1, b2};
    for (int L = 0; L < 2; L++) {
        const int C = HID_C, ld = KCHEB * HID_C;
        k_copy_h<<<(N_NODES * HID_C + 255) / 256, 256>>>();
        for (int k = 1; k < KCHEB; k++) {
            float alpha = (k == 1) ? 1.f : 2.f;
            float beta = (k >= 2) ? -1.f : 0.f;
            int ooff = (k >= 2) ? (k - 2) * C : 0;
            k_prop<<<N_NODES, C>>>((k - 1) * C, k * C, ooff, ld, alpha, beta);
        }
        k_gemm<<<ggrid, 256>>>(Ws[L], bs[L], ld, ld);
    }

    // ----- pool + output projection -----
    k_pool<<<N_NODES, 256>>>(batch);
    k_out<<<N_GRAPHS, OUT_C>>>(Wout, bout, out);
}

// round 4
// speedup vs baseline: 1.4864x; 1.4864x over previous
#include <cuda_runtime.h>
#include <cuda_bf16.h>
#include <cstdint>

#define N_NODES 10000
#define N_EDGES 320000
#define N_GRAPHS 64
#define KCHEB 10
#define IN_C 128
#define HID_C 256
#define OUT_C 128
#define KD_MAX (KCHEB * HID_C)  // 2560

// ---------------- scratch (static device globals; no allocs) ----------------
__device__ float g_Tcat[(size_t)N_NODES * KD_MAX];         // Chebyshev term stack (fp32)
__device__ __nv_bfloat16 g_Ahi[(size_t)N_NODES * KD_MAX];  // bf16 hi split of Tcat
__device__ __nv_bfloat16 g_Alo[(size_t)N_NODES * KD_MAX];  // bf16 lo split of Tcat
__device__ __nv_bfloat16 g_Bhi[(size_t)HID_C * KD_MAX];    // W^T hi  [256][Kd]
__device__ __nv_bfloat16 g_Blo[(size_t)HID_C * KD_MAX];    // W^T lo
__device__ float g_h[(size_t)N_NODES * HID_C];             // layer output (post ReLU)
__device__ float g_deg[N_NODES];
__device__ float g_dis[N_NODES];
__device__ int   g_rowcnt[N_NODES];
__device__ int   g_rowptr[N_NODES + 1];
__device__ int   g_cursor[N_NODES];
__device__ int   g_srcs[N_EDGES];
__device__ float g_ws[N_EDGES];
__device__ float g_pool[N_GRAPHS * HID_C];
__device__ float g_gcnt[N_GRAPHS];
__device__ int   g_is64;

// ---------------- helpers ----------------
__device__ __forceinline__ uint32_t smem_u32(const void* p) {
    uint32_t a;
    asm("{ .reg .u64 t; cvta.to.shared.u64 t, %1; cvt.u32.u64 %0, t; }" : "=r"(a) : "l"(p));
    return a;
}
__device__ __forceinline__ uint32_t sw128(uint32_t off) { return off ^ ((off >> 3) & 0x70); }

__device__ __forceinline__ void cp16(uint32_t dst, const void* src) {
    asm volatile("cp.async.cg.shared.global [%0], [%1], 16;" :: "r"(dst), "l"(src) : "memory");
}
#define CP_COMMIT() asm volatile("cp.async.commit_group;" ::: "memory")
#define CP_WAIT(N)  asm volatile("cp.async.wait_group %0;" :: "n"(N) : "memory")

__device__ __forceinline__ void ldsm4(uint32_t* r, uint32_t addr) {
    asm volatile("ldmatrix.sync.aligned.m8n8.x4.shared.b16 {%0,%1,%2,%3}, [%4];"
                 : "=r"(r[0]), "=r"(r[1]), "=r"(r[2]), "=r"(r[3]) : "r"(addr));
}
__device__ __forceinline__ void mma16816(float* c, const uint32_t* a, uint32_t b0, uint32_t b1) {
    asm volatile("mma.sync.aligned.m16n8k16.row.col.f32.bf16.bf16.f32 "
                 "{%0,%1,%2,%3}, {%4,%5,%6,%7}, {%8,%9}, {%0,%1,%2,%3};"
                 : "+f"(c[0]), "+f"(c[1]), "+f"(c[2]), "+f"(c[3])
                 : "r"(a[0]), "r"(a[1]), "r"(a[2]), "r"(a[3]), "r"(b0), "r"(b1));
}
__device__ __forceinline__ void split_store(float v, __nv_bfloat16* hi, __nv_bfloat16* lo, size_t idx) {
    __nv_bfloat16 h = __float2bfloat16(v);
    hi[idx] = h;
    lo[idx] = __float2bfloat16(v - __bfloat162float(h));
}

// ---------------- dtype detection ----------------
__global__ void k_detect(const int* __restrict__ ei_w) {
    if (threadIdx.x == 0 && blockIdx.x == 0) {
        int all0 = 1;
        for (int i = 0; i < 64; i++)
            if (ei_w[2 * i + 1] != 0) all0 = 0;
        g_is64 = all0;
    }
}
__device__ __forceinline__ int ld_edge(const int* __restrict__ w, int half, int e) {
    if (g_is64) return w[((size_t)half * N_EDGES + e) * 2];
    return w[half * N_EDGES + e];
}
__device__ __forceinline__ int ld_batch(const int* __restrict__ w, int n) {
    if (g_is64) return w[2 * n];
    return w[n];
}

// ---------------- prep kernels ----------------
__global__ void k_zero_prep() {
    int i = blockIdx.x * blockDim.x + threadIdx.x;
    if (i < N_NODES) { g_deg[i] = 0.f; g_rowcnt[i] = 0; }
    if (i < N_GRAPHS) g_gcnt[i] = 0.f;
    if (i < N_GRAPHS * HID_C) g_pool[i] = 0.f;
}
__global__ void k_count(const int* __restrict__ ei) {
    int e = blockIdx.x * blockDim.x + threadIdx.x;
    if (e >= N_EDGES) return;
    atomicAdd(&g_deg[ld_edge(ei, 0, e)], 1.f);
    atomicAdd(&g_rowcnt[ld_edge(ei, 1, e)], 1);
}
__global__ void k_dis() {
    int i = blockIdx.x * blockDim.x + threadIdx.x;
    if (i >= N_NODES) return;
    float d = g_deg[i];
    g_dis[i] = (d > 0.f) ? rsqrtf(d) : 0.f;
}
__global__ void k_scan() {
    __shared__ int sums[1024];
    int tid = threadIdx.x;
    const int per = (N_NODES + 1023) / 1024;
    int start = tid * per, local = 0;
    for (int i = 0; i < per; i++) { int idx = start + i; if (idx < N_NODES) local += g_rowcnt[idx]; }
    sums[tid] = local;
    __syncthreads();
    for (int off = 1; off < 1024; off <<= 1) {
        int v = 0;
        if (tid >= off) v = sums[tid - off];
        __syncthreads();
        if (tid >= off) sums[tid] += v;
        __syncthreads();
    }
    int prefix = (tid == 0) ? 0 : sums[tid - 1];
    for (int i = 0; i < per; i++) {
        int idx = start + i;
        if (idx < N_NODES) { g_rowptr[idx] = prefix; g_cursor[idx] = prefix; prefix += g_rowcnt[idx]; }
    }
    if (tid == 1023) g_rowptr[N_NODES] = sums[1023];
}
__global__ void k_fill(const int* __restrict__ ei) {
    int e = blockIdx.x * blockDim.x + threadIdx.x;
    if (e >= N_EDGES) return;
    int s = ld_edge(ei, 0, e);
    int d = ld_edge(ei, 1, e);
    int pos = atomicAdd(&g_cursor[d], 1);
    g_srcs[pos] = s;
    g_ws[pos] = -g_dis[s] * g_dis[d];
}

// ---------------- copies into the Chebyshev stack (fp32 + bf16 split) ----------------
__global__ void k_copy_x(const float* __restrict__ x) {
    int i = blockIdx.x * blockDim.x + threadIdx.x;
    if (i >= N_NODES * IN_C) return;
    int n = i / IN_C, c = i % IN_C;
    float v = x[i];
    size_t idx = (size_t)n * (KCHEB * IN_C) + c;
    g_Tcat[idx] = v;
    split_store(v, g_Ahi, g_Alo, idx);
}
__global__ void k_copy_h() {
    int i = blockIdx.x * blockDim.x + threadIdx.x;
    if (i >= N_NODES * HID_C) return;
    int n = i / HID_C, c = i % HID_C;
    float v = g_h[i];
    size_t idx = (size_t)n * (KCHEB * HID_C) + c;
    g_Tcat[idx] = v;
    split_store(v, g_Ahi, g_Alo, idx);
}

// ---------------- weight transpose + bf16 split: W[Kd][256] -> Bhi/Blo[256][Kd] ----------------
__global__ void k_split_w(const float* __restrict__ W, int Kd) {
    int i = blockIdx.x * blockDim.x + threadIdx.x;
    if (i >= HID_C * Kd) return;
    int n = i / Kd, k = i % Kd;
    split_store(W[(size_t)k * HID_C + n], g_Bhi, g_Blo, (size_t)n * Kd + k);
}

// ---------------- Chebyshev propagation (CSR gather) + on-the-fly bf16 split ----------------
__global__ void k_prop(int xoff, int yoff, int ooff, int ld, float alpha, float beta) {
    int n = blockIdx.x;
    int c = threadIdx.x;
    int C = blockDim.x;
    __shared__ int   s_src[128];
    __shared__ float s_w[128];
    int beg = g_rowptr[n], end = g_rowptr[n + 1];
    float acc = 0.f;
    for (int base = beg; base < end; base += 128) {
        int cnt = min(128, end - base);
        __syncthreads();
        for (int i = c; i < cnt; i += C) { s_src[i] = g_srcs[base + i]; s_w[i] = g_ws[base + i]; }
        __syncthreads();
        for (int i = 0; i < cnt; i++)
            acc += s_w[i] * g_Tcat[(size_t)s_src[i] * ld + xoff + c];
    }
    float r = alpha * acc;
    if (beta != 0.f) r += beta * g_Tcat[(size_t)n * ld + ooff + c];
    size_t idx = (size_t)n * ld + yoff + c;
    g_Tcat[idx] = r;
    split_store(r, g_Ahi, g_Alo, idx);
}

// ---------------- mma.sync GEMM: g_h = relu(Tcat[M,Kd] @ W[Kd,256] + bias) ----------------
// block 128x128, 8 warps (4M x 2N), warp tile 32x64. K chunks of 64 bf16.
// 3-pass bf16 split (hi*hi + hi*lo + lo*hi). cp.async double-buffered SMEM.
#define GM_TILE_BYTES  16384                  // 128 rows x 128B
#define GM_STAGE_BYTES (4 * GM_TILE_BYTES)    // Ahi, Alo, Bhi, Blo
#define GM_SMEM_TOTAL  (2 * GM_STAGE_BYTES)   // 128KB

__global__ void __launch_bounds__(256) k_gemm_mma(const float* __restrict__ bias, int Kd) {
    extern __shared__ char smem[];
    uint32_t sbase = smem_u32(smem);
    int tid = threadIdx.x;
    int lane = tid & 31, wid = tid >> 5;
    int wm = wid & 3, wn = wid >> 2;

    int col0 = blockIdx.x * 128;
    int row0 = blockIdx.y * 128;
    const int nchunks = Kd >> 6;

    const __nv_bfloat16* Ahi = g_Ahi;
    const __nv_bfloat16* Alo = g_Alo;
    const __nv_bfloat16* Bhi = g_Bhi;
    const __nv_bfloat16* Blo = g_Blo;

    float acc[2][8][4];
#pragma unroll
    for (int a = 0; a < 2; a++)
#pragma unroll
        for (int b = 0; b < 8; b++)
#pragma unroll
            for (int cq = 0; cq < 4; cq++) acc[a][b][cq] = 0.f;

    // stage loader: 4 tiles x 1024 16B-chunks, 256 threads -> 4 iters each
    auto load_stage = [&](int c) {
        int buf = c & 1;
        uint32_t toff = sbase + buf * GM_STAGE_BYTES;
        int k0 = c << 6;
#pragma unroll
        for (int i = 0; i < 4; i++) {
            int u = i * 256 + tid;
            int r = u >> 3, q = u & 7;
            uint32_t so = sw128((uint32_t)(r * 128 + q * 16));
            int ga = min(row0 + r, N_NODES - 1);   // clamp; garbage rows masked in epilogue
            int gb = col0 + r;
            size_t aoff = (size_t)ga * Kd + k0 + q * 8;
            size_t boff = (size_t)gb * Kd + k0 + q * 8;
            cp16(toff + 0 * GM_TILE_BYTES + so, Ahi + aoff);
            cp16(toff + 1 * GM_TILE_BYTES + so, Alo + aoff);
            cp16(toff + 2 * GM_TILE_BYTES + so, Bhi + boff);
            cp16(toff + 3 * GM_TILE_BYTES + so, Blo + boff);
        }
        CP_COMMIT();
    };

    load_stage(0);

    for (int c = 0; c < nchunks; c++) {
        if (c + 1 < nchunks) load_stage(c + 1);
        if (c + 1 < nchunks) { CP_WAIT(1); } else { CP_WAIT(0); }
        __syncthreads();

        int buf = c & 1;
        uint32_t toff = sbase + buf * GM_STAGE_BYTES;
        uint32_t offAhi = toff, offAlo = toff + GM_TILE_BYTES;
        uint32_t offBhi = toff + 2 * GM_TILE_BYTES, offBlo = toff + 3 * GM_TILE_BYTES;

        int arow = lane & 15, ahalf = lane >> 4;
#pragma unroll
        for (int ks = 0; ks < 4; ks++) {
            uint32_t colb = (uint32_t)(ks * 32 + ahalf * 16);
            uint32_t ah[2][4], al[2][4];
#pragma unroll
            for (int mi = 0; mi < 2; mi++) {
                uint32_t so = sw128((uint32_t)((wm * 32 + mi * 16 + arow) * 128) + colb);
                ldsm4(ah[mi], offAhi + so);
                ldsm4(al[mi], offAlo + so);
            }
#pragma unroll
            for (int nb = 0; nb < 4; nb++) {
                uint32_t so = sw128((uint32_t)((wn * 64 + nb * 16 + arow) * 128) + colb);
                uint32_t bh[4], bl[4];
                ldsm4(bh, offBhi + so);
                ldsm4(bl, offBlo + so);
#pragma unroll
                for (int mi = 0; mi < 2; mi++) {
                    float* c0 = acc[mi][nb * 2 + 0];
                    float* c1 = acc[mi][nb * 2 + 1];
                    mma16816(c0, ah[mi], bh[0], bh[2]);
                    mma16816(c1, ah[mi], bh[1], bh[3]);
                    mma16816(c0, ah[mi], bl[0], bl[2]);
                    mma16816(c1, ah[mi], bl[1], bl[3]);
                    mma16816(c0, al[mi], bh[0], bh[2]);
                    mma16816(c1, al[mi], bh[1], bh[3]);
                }
            }
        }
        __syncthreads();
    }

    // epilogue: bias + relu, direct fp32 stores
    int qr = lane >> 2, qc = (lane & 3) * 2;
#pragma unroll
    for (int mi = 0; mi < 2; mi++) {
#pragma unroll
        for (int nj = 0; nj < 8; nj++) {
            int gc = col0 + wn * 64 + nj * 8 + qc;
            float b0 = bias[gc], b1 = bias[gc + 1];
            int gr = row0 + wm * 32 + mi * 16 + qr;
            float* cc = acc[mi][nj];
            if (gr < N_NODES) {
                float2 v = make_float2(fmaxf(cc[0] + b0, 0.f), fmaxf(cc[1] + b1, 0.f));
                *(float2*)&g_h[(size_t)gr * HID_C + gc] = v;
            }
            if (gr + 8 < N_NODES) {
                float2 v = make_float2(fmaxf(cc[2] + b0, 0.f), fmaxf(cc[3] + b1, 0.f));
                *(float2*)&g_h[(size_t)(gr + 8) * HID_C + gc] = v;
            }
        }
    }
}

// ---------------- pooling + output GEMM ----------------
__global__ void k_pool(const int* __restrict__ batch) {
    int n = blockIdx.x;
    int g = ld_batch(batch, n);
    if (threadIdx.x == 0) atomicAdd(&g_gcnt[g], 1.f);
    for (int c = threadIdx.x; c < HID_C; c += blockDim.x)
        atomicAdd(&g_pool[g * HID_C + c], g_h[(size_t)n * HID_C + c]);
}
__global__ void k_out(const float* __restrict__ Wout, const float* __restrict__ bout,
                      float* __restrict__ out) {
    int g = blockIdx.x, o = threadIdx.x;
    float cn = fmaxf(g_gcnt[g], 1.f);
    float acc = 0.f;
    for (int k = 0; k < HID_C; k++)
        acc += g_pool[g * HID_C + k] * Wout[k * OUT_C + o];
    out[g * OUT_C + o] = acc / cn + bout[o];
}

// ---------------- driver ----------------
extern "C" void kernel_launch(void* const* d_in, const int* in_sizes, int n_in,
                              void* d_out, int out_size) {
    const float* x = (const float*)d_in[0];
    const float* W0 = (const float*)d_in[1];
    const float* b0 = (const float*)d_in[2];
    const float* W1 = (const float*)d_in[3];
    const float* b1 = (const float*)d_in[4];
    const float* W2 = (const float*)d_in[5];
    const float* b2 = (const float*)d_in[6];
    const float* Wout = (const float*)d_in[7];
    const float* bout = (const float*)d_in[8];
    const int* ei = (const int*)d_in[9];
    const int* batch = (const int*)d_in[10];
    float* out = (float*)d_out;

    cudaFuncSetAttribute(k_gemm_mma, cudaFuncAttributeMaxDynamicSharedMemorySize, GM_SMEM_TOTAL);

    k_detect<<<1, 32>>>(ei);
    k_zero_prep<<<64, 256>>>();
    k_count<<<(N_EDGES + 255) / 256, 256>>>(ei);
    k_dis<<<(N_NODES + 255) / 256, 256>>>();
    k_scan<<<1, 1024>>>();
    k_fill<<<(N_EDGES + 255) / 256, 256>>>(ei);

    dim3 ggrid(2, (N_NODES + 127) / 128);

    // ----- layer 0 (C_in = 128, Kd = 1280) -----
    {
        const int C = IN_C, ld = KCHEB * IN_C;
        k_copy_x<<<(N_NODES * IN_C + 255) / 256, 256>>>(x);
        k_split_w<<<(HID_C * ld + 255) / 256, 256>>>(W0, ld);
        for (int k = 1; k < KCHEB; k++) {
            float alpha = (k == 1) ? 1.f : 2.f;
            float beta = (k >= 2) ? -1.f : 0.f;
            int ooff = (k >= 2) ? (k - 2) * C : 0;
            k_prop<<<N_NODES, C>>>((k - 1) * C, k * C, ooff, ld, alpha, beta);
        }
        k_gemm_mma<<<ggrid, 256, GM_SMEM_TOTAL>>>(b0, ld);
    }

    // ----- layers 1, 2 (C_in = 256, Kd = 2560) -----
    const float* Ws[2] = {W1, W2};
    const float* bs[2] = {b1, b2};
    for (int L = 0; L < 2; L++) {
        const int C = HID_C, ld = KCHEB * HID_C;
        k_copy_h<<<(N_NODES * HID_C + 255) / 256, 256>>>();
        k_split_w<<<(HID_C * ld + 255) / 256, 256>>>(Ws[L], ld);
        for (int k = 1; k < KCHEB; k++) {
            float alpha = (k == 1) ? 1.f : 2.f;
            float beta = (k >= 2) ? -1.f : 0.f;
            int ooff = (k >= 2) ? (k - 2) * C : 0;
            k_prop<<<N_NODES, C>>>((k - 1) * C, k * C, ooff, ld, alpha, beta);
        }
        k_gemm_mma<<<ggrid, 256, GM_SMEM_TOTAL>>>(bs[L], ld);
    }

    // ----- pool + output projection -----
    k_pool<<<N_NODES, 256>>>(batch);
    k_out<<<N_GRAPHS, OUT_C>>>(Wout, bout, out);
}

// round 5
// speedup vs baseline: 1.6666x; 1.1212x over previous
#include <cuda_runtime.h>
#include <cuda_bf16.h>
#include <cstdint>

#define N_NODES 10000
#define N_EDGES 320000
#define N_GRAPHS 64
#define KCHEB 10
#define IN_C 128
#define HID_C 256
#define OUT_C 128
#define KD_MAX (KCHEB * HID_C)  // 2560

// ---------------- scratch (static device globals; no allocs) ----------------
__device__ float g_Tcat[(size_t)N_NODES * KD_MAX];         // Chebyshev term stack (fp32)
__device__ __nv_bfloat16 g_Ahi[(size_t)N_NODES * KD_MAX];  // bf16 hi split of Tcat
__device__ __nv_bfloat16 g_Alo[(size_t)N_NODES * KD_MAX];  // bf16 lo split of Tcat
__device__ __nv_bfloat16 g_Bhi[(size_t)HID_C * KD_MAX];    // W^T hi  [256][Kd]
__device__ __nv_bfloat16 g_Blo[(size_t)HID_C * KD_MAX];    // W^T lo
__device__ float g_h[(size_t)N_NODES * HID_C];             // layer output (post ReLU)
__device__ float g_deg[N_NODES];
__device__ float g_dis[N_NODES];
__device__ int   g_rowcnt[N_NODES];
__device__ int   g_rowptr[N_NODES + 1];
__device__ int   g_cursor[N_NODES];
__device__ int2  g_edge[N_EDGES];          // packed (src, w-bits) CSR by dst
__device__ float g_pool[N_GRAPHS * HID_C];
__device__ float g_gcnt[N_GRAPHS];
__device__ int   g_is64;

// ---------------- helpers ----------------
__device__ __forceinline__ uint32_t smem_u32(const void* p) {
    uint32_t a;
    asm("{ .reg .u64 t; cvta.to.shared.u64 t, %1; cvt.u32.u64 %0, t; }" : "=r"(a) : "l"(p));
    return a;
}
__device__ __forceinline__ uint32_t sw64(uint32_t off) { return off ^ ((off >> 3) & 0x30); }

__device__ __forceinline__ void cp16(uint32_t dst, const void* src) {
    asm volatile("cp.async.cg.shared.global [%0], [%1], 16;" :: "r"(dst), "l"(src) : "memory");
}
#define CP_COMMIT() asm volatile("cp.async.commit_group;" ::: "memory")
#define CP_WAIT(N)  asm volatile("cp.async.wait_group %0;" :: "n"(N) : "memory")

__device__ __forceinline__ void ldsm4(uint32_t* r, uint32_t addr) {
    asm volatile("ldmatrix.sync.aligned.m8n8.x4.shared.b16 {%0,%1,%2,%3}, [%4];"
                 : "=r"(r[0]), "=r"(r[1]), "=r"(r[2]), "=r"(r[3]) : "r"(addr));
}
__device__ __forceinline__ void mma16816(float* c, const uint32_t* a, uint32_t b0, uint32_t b1) {
    asm volatile("mma.sync.aligned.m16n8k16.row.col.f32.bf16.bf16.f32 "
                 "{%0,%1,%2,%3}, {%4,%5,%6,%7}, {%8,%9}, {%0,%1,%2,%3};"
                 : "+f"(c[0]), "+f"(c[1]), "+f"(c[2]), "+f"(c[3])
                 : "r"(a[0]), "r"(a[1]), "r"(a[2]), "r"(a[3]), "r"(b0), "r"(b1));
}
__device__ __forceinline__ void split_store(float v, __nv_bfloat16* hi, __nv_bfloat16* lo, size_t idx) {
    __nv_bfloat16 h = __float2bfloat16(v);
    hi[idx] = h;
    lo[idx] = __float2bfloat16(v - __bfloat162float(h));
}

// ---------------- dtype detection ----------------
__global__ void k_detect(const int* __restrict__ ei_w) {
    if (threadIdx.x == 0 && blockIdx.x == 0) {
        int all0 = 1;
        for (int i = 0; i < 64; i++)
            if (ei_w[2 * i + 1] != 0) all0 = 0;
        g_is64 = all0;
    }
}
__device__ __forceinline__ int ld_edge(const int* __restrict__ w, int half, int e) {
    if (g_is64) return w[((size_t)half * N_EDGES + e) * 2];
    return w[half * N_EDGES + e];
}
__device__ __forceinline__ int ld_batch(const int* __restrict__ w, int n) {
    if (g_is64) return w[2 * n];
    return w[n];
}

// ---------------- prep kernels ----------------
__global__ void k_zero_prep() {
    int i = blockIdx.x * blockDim.x + threadIdx.x;
    if (i < N_NODES) { g_deg[i] = 0.f; g_rowcnt[i] = 0; }
    if (i < N_GRAPHS) g_gcnt[i] = 0.f;
    if (i < N_GRAPHS * HID_C) g_pool[i] = 0.f;
}
__global__ void k_count(const int* __restrict__ ei) {
    int e = blockIdx.x * blockDim.x + threadIdx.x;
    if (e >= N_EDGES) return;
    atomicAdd(&g_deg[ld_edge(ei, 0, e)], 1.f);
    atomicAdd(&g_rowcnt[ld_edge(ei, 1, e)], 1);
}
__global__ void k_dis() {
    int i = blockIdx.x * blockDim.x + threadIdx.x;
    if (i >= N_NODES) return;
    float d = g_deg[i];
    g_dis[i] = (d > 0.f) ? rsqrtf(d) : 0.f;
}
__global__ void k_scan() {
    __shared__ int sums[1024];
    int tid = threadIdx.x;
    const int per = (N_NODES + 1023) / 1024;
    int start = tid * per, local = 0;
    for (int i = 0; i < per; i++) { int idx = start + i; if (idx < N_NODES) local += g_rowcnt[idx]; }
    sums[tid] = local;
    __syncthreads();
    for (int off = 1; off < 1024; off <<= 1) {
        int v = 0;
        if (tid >= off) v = sums[tid - off];
        __syncthreads();
        if (tid >= off) sums[tid] += v;
        __syncthreads();
    }
    int prefix = (tid == 0) ? 0 : sums[tid - 1];
    for (int i = 0; i < per; i++) {
        int idx = start + i;
        if (idx < N_NODES) { g_rowptr[idx] = prefix; g_cursor[idx] = prefix; prefix += g_rowcnt[idx]; }
    }
    if (tid == 1023) g_rowptr[N_NODES] = sums[1023];
}
__global__ void k_fill(const int* __restrict__ ei) {
    int e = blockIdx.x * blockDim.x + threadIdx.x;
    if (e >= N_EDGES) return;
    int s = ld_edge(ei, 0, e);
    int d = ld_edge(ei, 1, e);
    int pos = atomicAdd(&g_cursor[d], 1);
    float w = -g_dis[s] * g_dis[d];
    g_edge[pos] = make_int2(s, __float_as_int(w));
}

// ---------------- copies into the Chebyshev stack (fp32 + bf16 split) ----------------
__global__ void k_copy_x(const float* __restrict__ x) {
    int i = blockIdx.x * blockDim.x + threadIdx.x;
    if (i >= N_NODES * IN_C) return;
    int n = i / IN_C, c = i % IN_C;
    float v = x[i];
    size_t idx = (size_t)n * (KCHEB * IN_C) + c;
    g_Tcat[idx] = v;
    split_store(v, g_Ahi, g_Alo, idx);
}
__global__ void k_copy_h() {
    int i = blockIdx.x * blockDim.x + threadIdx.x;
    if (i >= N_NODES * HID_C) return;
    int n = i / HID_C, c = i % HID_C;
    float v = g_h[i];
    size_t idx = (size_t)n * (KCHEB * HID_C) + c;
    g_Tcat[idx] = v;
    split_store(v, g_Ahi, g_Alo, idx);
}

// ---------------- weight transpose + bf16 split: W[Kd][256] -> Bhi/Blo[256][Kd] ----------------
__global__ void k_split_w(const float* __restrict__ W, int Kd) {
    int i = blockIdx.x * blockDim.x + threadIdx.x;
    if (i >= HID_C * Kd) return;
    int n = i / Kd, k = i % Kd;
    split_store(W[(size_t)k * HID_C + n], g_Bhi, g_Blo, (size_t)n * Kd + k);
}

// ---------------- Chebyshev propagation: float4 gather, 4 nodes/block ----------------
// blockDim = (C/4, 4); grid = N_NODES/4
__global__ void k_prop(int xoff, int yoff, int ooff, int ld, float alpha, float beta) {
    int n = blockIdx.x * 4 + threadIdx.y;
    int cx = threadIdx.x;                      // column quad index
    const float* Xb = g_Tcat + xoff + 4 * cx;
    int beg = g_rowptr[n], end = g_rowptr[n + 1];
    int cnt = end - beg;
    float ax = 0.f, ay = 0.f, az = 0.f, aw = 0.f;
#pragma unroll 4
    for (int i = 0; i < cnt; i++) {
        int2 m = __ldg(&g_edge[beg + i]);
        float w = __int_as_float(m.y);
        const float4 v = *(const float4*)(Xb + (size_t)m.x * ld);
        ax += w * v.x; ay += w * v.y; az += w * v.z; aw += w * v.w;
    }
    float4 r = make_float4(alpha * ax, alpha * ay, alpha * az, alpha * aw);
    if (beta != 0.f) {
        float4 o = *(const float4*)(g_Tcat + (size_t)n * ld + ooff + 4 * cx);
        r.x += beta * o.x; r.y += beta * o.y; r.z += beta * o.z; r.w += beta * o.w;
    }
    size_t idx = (size_t)n * ld + yoff + 4 * cx;
    *(float4*)(g_Tcat + idx) = r;
    split_store(r.x, g_Ahi, g_Alo, idx + 0);
    split_store(r.y, g_Ahi, g_Alo, idx + 1);
    split_store(r.z, g_Ahi, g_Alo, idx + 2);
    split_store(r.w, g_Ahi, g_Alo, idx + 3);
}

// ---------------- mma.sync GEMM v2: BM=192, BN=128, K-chunk 32, SW64, 3 stages ----------------
// 8 warps: 4M (48 rows each) x 2N (64 cols each). grid = (2, 53) = 106 CTAs.
#define GM_BM 192
#define GM_AT_BYTES (GM_BM * 64)             // 12288 per A tile
#define GM_BT_BYTES (128 * 64)               // 8192 per B tile
#define GM_STAGE    (2 * GM_AT_BYTES + 2 * GM_BT_BYTES)  // 40960
#define GM_NSTAGES  3
#define GM_SMEM_TOTAL (GM_NSTAGES * GM_STAGE)            // 122880

__global__ void __launch_bounds__(256) k_gemm_mma(const float* __restrict__ bias, int Kd) {
    extern __shared__ char smem[];
    uint32_t sbase = smem_u32(smem);
    int tid = threadIdx.x;
    int lane = tid & 31, wid = tid >> 5;
    int wm = wid & 3, wn = wid >> 2;

    int col0 = blockIdx.x * 128;
    int row0 = blockIdx.y * GM_BM;
    const int nchunks = Kd >> 5;  // K chunks of 32

    const __nv_bfloat16* Ahi = g_Ahi;
    const __nv_bfloat16* Alo = g_Alo;
    const __nv_bfloat16* Bhi = g_Bhi;
    const __nv_bfloat16* Blo = g_Blo;

    float acc[3][8][4];
#pragma unroll
    for (int a = 0; a < 3; a++)
#pragma unroll
        for (int b = 0; b < 8; b++)
#pragma unroll
            for (int cq = 0; cq < 4; cq++) acc[a][b][cq] = 0.f;

    // stage loader: 2560 16B-chunks (A:768x2, B:512x2); 256 threads -> 10 each
    auto load_stage = [&](int c) {
        uint32_t toff = sbase + (c % GM_NSTAGES) * GM_STAGE;
        int k0 = c << 5;
#pragma unroll
        for (int i = 0; i < 10; i++) {
            int u = i * 256 + tid;
            if (u < 1536) {                       // A tiles
                int t = u >> 9;                   // 0..2 over 512-chunk halves... (768 per tile)
                int v = u;
                const __nv_bfloat16* src;
                uint32_t tb;
                if (v < 768) { src = Ahi; tb = 0; }
                else { src = Alo; v -= 768; tb = GM_AT_BYTES; }
                int r = v >> 2, q = v & 3;
                int ga = min(row0 + r, N_NODES - 1);
                cp16(toff + tb + sw64((uint32_t)(r * 64 + q * 16)),
                     src + (size_t)ga * Kd + k0 + q * 8);
                (void)t;
            } else {                              // B tiles
                int v = u - 1536;
                const __nv_bfloat16* src;
                uint32_t tb;
                if (v < 512) { src = Bhi; tb = 2 * GM_AT_BYTES; }
                else { src = Blo; v -= 512; tb = 2 * GM_AT_BYTES + GM_BT_BYTES; }
                int r = v >> 2, q = v & 3;
                int gb = col0 + r;
                cp16(toff + tb + sw64((uint32_t)(r * 64 + q * 16)),
                     src + (size_t)gb * Kd + k0 + q * 8);
            }
        }
        CP_COMMIT();
    };

    load_stage(0);
    if (nchunks > 1) load_stage(1);

    int arow = lane & 15, ahalf = lane >> 4;

    for (int c = 0; c < nchunks; c++) {
        if (c + 1 < nchunks) { CP_WAIT(1); } else { CP_WAIT(0); }
        __syncthreads();
        if (c + 2 < nchunks) load_stage(c + 2);

        uint32_t toff = sbase + (c % GM_NSTAGES) * GM_STAGE;
        uint32_t offAhi = toff, offAlo = toff + GM_AT_BYTES;
        uint32_t offBhi = toff + 2 * GM_AT_BYTES, offBlo = offBhi + GM_BT_BYTES;

#pragma unroll
        for (int ks = 0; ks < 2; ks++) {
            uint32_t colb = (uint32_t)(ks * 32 + ahalf * 16);
            uint32_t ah[3][4], al[3][4];
#pragma unroll
            for (int mi = 0; mi < 3; mi++) {
                uint32_t so = sw64((uint32_t)((wm * 48 + mi * 16 + arow) * 64) + colb);
                ldsm4(ah[mi], offAhi + so);
                ldsm4(al[mi], offAlo + so);
            }
#pragma unroll
            for (int nb = 0; nb < 4; nb++) {
                uint32_t so = sw64((uint32_t)((wn * 64 + nb * 16 + arow) * 64) + colb);
                uint32_t bh[4], bl[4];
                ldsm4(bh, offBhi + so);
                ldsm4(bl, offBlo + so);
#pragma unroll
                for (int mi = 0; mi < 3; mi++) {
                    float* c0 = acc[mi][nb * 2 + 0];
                    float* c1 = acc[mi][nb * 2 + 1];
                    mma16816(c0, ah[mi], bh[0], bh[2]);
                    mma16816(c1, ah[mi], bh[1], bh[3]);
                    mma16816(c0, ah[mi], bl[0], bl[2]);
                    mma16816(c1, ah[mi], bl[1], bl[3]);
                    mma16816(c0, al[mi], bh[0], bh[2]);
                    mma16816(c1, al[mi], bh[1], bh[3]);
                }
            }
        }
        __syncthreads();
    }

    // epilogue: bias + relu, direct fp32 stores
    int qr = lane >> 2, qc = (lane & 3) * 2;
#pragma unroll
    for (int mi = 0; mi < 3; mi++) {
#pragma unroll
        for (int nj = 0; nj < 8; nj++) {
            int gc = col0 + wn * 64 + nj * 8 + qc;
            float b0 = bias[gc], b1 = bias[gc + 1];
            int gr = row0 + wm * 48 + mi * 16 + qr;
            float* cc = acc[mi][nj];
            if (gr < N_NODES) {
                float2 v = make_float2(fmaxf(cc[0] + b0, 0.f), fmaxf(cc[1] + b1, 0.f));
                *(float2*)&g_h[(size_t)gr * HID_C + gc] = v;
            }
            if (gr + 8 < N_NODES) {
                float2 v = make_float2(fmaxf(cc[2] + b0, 0.f), fmaxf(cc[3] + b1, 0.f));
                *(float2*)&g_h[(size_t)(gr + 8) * HID_C + gc] = v;
            }
        }
    }
}

// ---------------- pooling + output GEMM ----------------
__global__ void k_pool(const int* __restrict__ batch) {
    int n = blockIdx.x;
    int g = ld_batch(batch, n);
    if (threadIdx.x == 0) atomicAdd(&g_gcnt[g], 1.f);
    for (int c = threadIdx.x; c < HID_C; c += blockDim.x)
        atomicAdd(&g_pool[g * HID_C + c], g_h[(size_t)n * HID_C + c]);
}
__global__ void k_out(const float* __restrict__ Wout, const float* __restrict__ bout,
                      float* __restrict__ out) {
    int g = blockIdx.x, o = threadIdx.x;
    float cn = fmaxf(g_gcnt[g], 1.f);
    float acc = 0.f;
    for (int k = 0; k < HID_C; k++)
        acc += g_pool[g * HID_C + k] * Wout[k * OUT_C + o];
    out[g * OUT_C + o] = acc / cn + bout[o];
}

// ---------------- driver ----------------
extern "C" void kernel_launch(void* const* d_in, const int* in_sizes, int n_in,
                              void* d_out, int out_size) {
    const float* x = (const float*)d_in[0];
    const float* W0 = (const float*)d_in[1];
    const float* b0 = (const float*)d_in[2];
    const float* W1 = (const float*)d_in[3];
    const float* b1 = (const float*)d_in[4];
    const float* W2 = (const float*)d_in[5];
    const float* b2 = (const float*)d_in[6];
    const float* Wout = (const float*)d_in[7];
    const float* bout = (const float*)d_in[8];
    const int* ei = (const int*)d_in[9];
    const int* batch = (const int*)d_in[10];
    float* out = (float*)d_out;

    cudaFuncSetAttribute(k_gemm_mma, cudaFuncAttributeMaxDynamicSharedMemorySize, GM_SMEM_TOTAL);

    k_detect<<<1, 32>>>(ei);
    k_zero_prep<<<64, 256>>>();
    k_count<<<(N_EDGES + 255) / 256, 256>>>(ei);
    k_dis<<<(N_NODES + 255) / 256, 256>>>();
    k_scan<<<1, 1024>>>();
    k_fill<<<(N_EDGES + 255) / 256, 256>>>(ei);

    dim3 ggrid(2, (N_NODES + GM_BM - 1) / GM_BM);

    // ----- layer 0 (C_in = 128, Kd = 1280) -----
    {
        const int C = IN_C, ld = KCHEB * IN_C;
        k_copy_x<<<(N_NODES * IN_C + 255) / 256, 256>>>(x);
        k_split_w<<<(HID_C * ld + 255) / 256, 256>>>(W0, ld);
        dim3 pb(C / 4, 4);
        for (int k = 1; k < KCHEB; k++) {
            float alpha = (k == 1) ? 1.f : 2.f;
            float beta = (k >= 2) ? -1.f : 0.f;
            int ooff = (k >= 2) ? (k - 2) * C : 0;
            k_prop<<<N_NODES / 4, pb>>>((k - 1) * C, k * C, ooff, ld, alpha, beta);
        }
        k_gemm_mma<<<ggrid, 256, GM_SMEM_TOTAL>>>(b0, ld);
    }

    // ----- layers 1, 2 (C_in = 256, Kd = 2560) -----
    const float* Ws[2] = {W1, W2};
    const float* bs[2] = {b1, b2};
    for (int L = 0; L < 2; L++) {
        const int C = HID_C, ld = KCHEB * HID_C;
        k_copy_h<<<(N_NODES * HID_C + 255) / 256, 256>>>();
        k_split_w<<<(HID_C * ld + 255) / 256, 256>>>(Ws[L], ld);
        dim3 pb(C / 4, 4);
        for (int k = 1; k < KCHEB; k++) {
            float alpha = (k == 1) ? 1.f : 2.f;
            float beta = (k >= 2) ? -1.f : 0.f;
            int ooff = (k >= 2) ? (k - 2) * C : 0;
            k_prop<<<N_NODES / 4, pb>>>((k - 1) * C, k * C, ooff, ld, alpha, beta);
        }
        k_gemm_mma<<<ggrid, 256, GM_SMEM_TOTAL>>>(bs[L], ld);
    }

    // ----- pool + output projection -----
    k_pool<<<N_NODES, 256>>>(batch);
    k_out<<<N_GRAPHS, OUT_C>>>(Wout, bout, out);
}